// round 9
// baseline (speedup 1.0000x reference)
#include <cuda_runtime.h>
#include <cstdint>
#include <cstddef>

#define SS 2048
#define DD 64
#define HH 16

// per-(bh,row,ktile) partial sums of exp(score):  32 * 2048 * 16 floats = 4MB
__device__ float g_rowpart[(size_t)32 * 2048 * 16];

static __device__ __forceinline__ float2 ffma2(float2 a, float2 b, float2 c) {
    unsigned long long ua = *reinterpret_cast<unsigned long long*>(&a);
    unsigned long long ub = *reinterpret_cast<unsigned long long*>(&b);
    unsigned long long uc = *reinterpret_cast<unsigned long long*>(&c);
    unsigned long long ud;
    asm("fma.rn.f32x2 %0, %1, %2, %3;" : "=l"(ud) : "l"(ua), "l"(ub), "l"(uc));
    return *reinterpret_cast<float2*>(&ud);
}

// T5 bidirectional bucket, NUM_BUCKETS=32, MAX_DISTANCE=128 (exact int thresholds)
static __device__ __forceinline__ int rp_bucket(int rel) {
    int n = -rel;
    int ret = (n < 0) ? 16 : 0;
    n = abs(n);
    if (n < 8) return ret + n;
    return ret + 8 + (n >= 12) + (n >= 16) + (n >= 23) + (n >= 32)
                   + (n >= 46) + (n >= 64) + (n >= 91);
}

// K1: QK^T/8 + bias, masked -> writes exp(score) to attn buf, bias to pb,
//     and per-(row,ktile) partial sum of exp to g_rowpart.
__global__ __launch_bounds__(256) void k1_scores(
    const float* __restrict__ qg, const float* __restrict__ kg,
    const float* __restrict__ bw, const int* __restrict__ ctx,
    const int* __restrict__ mem, const unsigned int* __restrict__ mask,
    float* __restrict__ attn, float* __restrict__ pb)
{
    extern __shared__ float smx[];
    float* Qs = smx;               // [64][132] d-major, swizzled rows
    float* Ks = smx + 64 * 132;
    __shared__ float bwsh[32];

    const int tid = threadIdx.x;
    const int kt = blockIdx.x, qt = blockIdx.y, bh = blockIdx.z;
    const int b = bh >> 4, h = bh & 15;
    if (tid < 32) bwsh[tid] = bw[tid * HH + h];

    const float4* qv = (const float4*)(qg + ((size_t)bh * SS + (size_t)qt * 128) * DD);
    const float4* kv = (const float4*)(kg + ((size_t)bh * SS + (size_t)kt * 128) * DD);
#pragma unroll
    for (int rep = 0; rep < 8; rep++) {
        int i4 = rep * 256 + tid;
        int row = i4 >> 4;
        int c4 = (i4 & 15) << 2;
        float4 a = qv[i4], bv = kv[i4];
        int r = row ^ (((c4 >> 2) & 7) << 2);
        Qs[(c4+0)*132 + r] = a.x;  Qs[(c4+1)*132 + r] = a.y;
        Qs[(c4+2)*132 + r] = a.z;  Qs[(c4+3)*132 + r] = a.w;
        Ks[(c4+0)*132 + r] = bv.x; Ks[(c4+1)*132 + r] = bv.y;
        Ks[(c4+2)*132 + r] = bv.z; Ks[(c4+3)*132 + r] = bv.w;
    }
    __syncthreads();

    const int ty = tid >> 4, tx = tid & 15;
    const int qr = ty << 3, kc = tx << 3;
    float2 acc[8][4];
#pragma unroll
    for (int i = 0; i < 8; i++)
#pragma unroll
        for (int j = 0; j < 4; j++) acc[i][j] = make_float2(0.f, 0.f);

#pragma unroll 8
    for (int d = 0; d < 64; d++) {
        const float* Qd = Qs + d * 132;
        const float* Kd = Ks + d * 132;
        int fd = ((d >> 2) & 7) << 2;
        int rq = qr ^ fd, rk = kc ^ fd;
        float4 a0 = *(const float4*)(Qd + rq);
        float4 a1 = *(const float4*)(Qd + (rq ^ 4));
        float4 b0 = *(const float4*)(Kd + rk);
        float4 b1 = *(const float4*)(Kd + (rk ^ 4));
        float2 bp0 = make_float2(b0.x, b0.y), bp1 = make_float2(b0.z, b0.w);
        float2 bp2 = make_float2(b1.x, b1.y), bp3 = make_float2(b1.z, b1.w);
        float av[8] = {a0.x,a0.y,a0.z,a0.w,a1.x,a1.y,a1.z,a1.w};
#pragma unroll
        for (int i = 0; i < 8; i++) {
            float2 ap = make_float2(av[i], av[i]);
            acc[i][0] = ffma2(ap, bp0, acc[i][0]);
            acc[i][1] = ffma2(ap, bp1, acc[i][1]);
            acc[i][2] = ffma2(ap, bp2, acc[i][2]);
            acc[i][3] = ffma2(ap, bp3, acc[i][3]);
        }
    }

    const int qi0 = qt * 128 + qr;
    const int kj0 = kt * 128 + kc;
    int ctxv[8], memv[8];
#pragma unroll
    for (int i = 0; i < 8; i++) ctxv[i] = ctx[b * SS + qi0 + i];
#pragma unroll
    for (int j = 0; j < 8; j++) memv[j] = mem[b * SS + kj0 + j];

#pragma unroll
    for (int i = 0; i < 8; i++) {
        const int qi = qi0 + i;
        const size_t off = ((size_t)bh * SS + qi) * SS + kj0;
        const uint4 m0 = *(const uint4*)(mask + ((size_t)b * SS + qi) * SS + kj0);
        const uint4 m1 = *(const uint4*)(mask + ((size_t)b * SS + qi) * SS + kj0 + 4);
        unsigned int mw[8] = {m0.x, m0.y, m0.z, m0.w, m1.x, m1.y, m1.z, m1.w};
        float ev[8], pv[8];
#pragma unroll
        for (int j = 0; j < 8; j++) {
            float bias = bwsh[rp_bucket(memv[j] - ctxv[i])];
            pv[j] = bias;
            float s = ((j & 1) ? acc[i][j >> 1].y : acc[i][j >> 1].x) * 0.125f + bias;
            ev[j] = (mw[j] != 0u) ? 0.0f : __expf(s);
        }
        *(float4*)(attn + off)     = make_float4(ev[0], ev[1], ev[2], ev[3]);
        *(float4*)(attn + off + 4) = make_float4(ev[4], ev[5], ev[6], ev[7]);
        *(float4*)(pb + off)       = make_float4(pv[0], pv[1], pv[2], pv[3]);
        *(float4*)(pb + off + 4)   = make_float4(pv[4], pv[5], pv[6], pv[7]);

        // partial row sum across the 16 tx lanes
        float ps = ev[0]+ev[1]+ev[2]+ev[3]+ev[4]+ev[5]+ev[6]+ev[7];
        ps += __shfl_xor_sync(0xffffffffu, ps, 1);
        ps += __shfl_xor_sync(0xffffffffu, ps, 2);
        ps += __shfl_xor_sync(0xffffffffu, ps, 4);
        ps += __shfl_xor_sync(0xffffffffu, ps, 8);
        if (tx == 0)
            g_rowpart[((size_t)bh * SS + qi) * 16 + kt] = ps;
    }
}

// K3: normalize attn in-place + output = attn @ V.
// 128 threads, tile 128q x 64d, micro 8x8.  A in smem k-major (swizzled rows).
__global__ __launch_bounds__(128) void k3_av(
    float* __restrict__ attn, const float* __restrict__ vg,
    float* __restrict__ outp)
{
    extern __shared__ float smx[];
    float* As = smx;               // [64 k][132 q] swizzled
    float* Vs = smx + 64 * 132;    // [64 k][68 d]
    __shared__ float rowInv[128];

    const int tid = threadIdx.x;
    const int qt = blockIdx.x, bh = blockIdx.y;
    const int ty = tid >> 3, tx = tid & 7;
    const int qr = ty << 3, dc = tx << 3;

    {
        const float* pp = g_rowpart + ((size_t)bh * SS + (size_t)qt * 128 + tid) * 16;
        float s = 0.f;
#pragma unroll
        for (int t = 0; t < 16; t++) s += pp[t];
        rowInv[tid] = 1.0f / s;
    }
    __syncthreads();

    float2 acc[8][4];
#pragma unroll
    for (int i = 0; i < 8; i++)
#pragma unroll
        for (int j = 0; j < 4; j++) acc[i][j] = make_float2(0.f, 0.f);

    for (int kt = 0; kt < 32; kt++) {
        float4* asrc = (float4*)(attn + ((size_t)bh * SS + (size_t)qt * 128) * SS + kt * 64);
        const float4* vsrc = (const float4*)(vg + ((size_t)bh * SS + (size_t)kt * 64) * DD);

        // A tile: load 128q x 64k, normalize, write back, store k-major swizzled
#pragma unroll
        for (int rep = 0; rep < 16; rep++) {
            int i4 = rep * 128 + tid;
            int row = i4 >> 4;            // q row 0..127
            int c4 = (i4 & 15) << 2;      // k offset 0..60
            float4 e = asrc[row * 512 + (c4 >> 2)];
            float inv = rowInv[row];
            e.x *= inv; e.y *= inv; e.z *= inv; e.w *= inv;
            asrc[row * 512 + (c4 >> 2)] = e;
            int r = row ^ (((c4 >> 2) & 7) << 2);
            As[(c4+0)*132 + r] = e.x;  As[(c4+1)*132 + r] = e.y;
            As[(c4+2)*132 + r] = e.z;  As[(c4+3)*132 + r] = e.w;
        }
        // V tile: 64k x 64d row-major
#pragma unroll
        for (int rep = 0; rep < 8; rep++) {
            int i4 = rep * 128 + tid;
            int row = i4 >> 4, c4 = (i4 & 15) << 2;
            *(float4*)(Vs + row * 68 + c4) = vsrc[row * 16 + (c4 >> 2)];
        }
        __syncthreads();

#pragma unroll 8
        for (int k = 0; k < 64; k++) {
            const float* Ak = As + k * 132;
            const float* Vk = Vs + k * 68 + dc;
            int fk = ((k >> 2) & 7) << 2;
            int rq = qr ^ fk;
            float4 a0 = *(const float4*)(Ak + rq);
            float4 a1 = *(const float4*)(Ak + (rq ^ 4));
            float4 v0 = *(const float4*)(Vk);
            float4 v1 = *(const float4*)(Vk + 4);
            float2 vp0 = make_float2(v0.x, v0.y), vp1 = make_float2(v0.z, v0.w);
            float2 vp2 = make_float2(v1.x, v1.y), vp3 = make_float2(v1.z, v1.w);
            float av[8] = {a0.x,a0.y,a0.z,a0.w,a1.x,a1.y,a1.z,a1.w};
#pragma unroll
            for (int i = 0; i < 8; i++) {
                float2 ap = make_float2(av[i], av[i]);
                acc[i][0] = ffma2(ap, vp0, acc[i][0]);
                acc[i][1] = ffma2(ap, vp1, acc[i][1]);
                acc[i][2] = ffma2(ap, vp2, acc[i][2]);
                acc[i][3] = ffma2(ap, vp3, acc[i][3]);
            }
        }
        __syncthreads();
    }

#pragma unroll
    for (int i = 0; i < 8; i++) {
        size_t off = ((size_t)bh * SS + (size_t)qt * 128 + qr + i) * DD + dc;
        *(float4*)(outp + off)     = make_float4(acc[i][0].x, acc[i][0].y, acc[i][1].x, acc[i][1].y);
        *(float4*)(outp + off + 4) = make_float4(acc[i][2].x, acc[i][2].y, acc[i][3].x, acc[i][3].y);
    }
}

extern "C" void kernel_launch(void* const* d_in, const int* in_sizes, int n_in,
                              void* d_out, int out_size)
{
    const float* q  = (const float*)d_in[0];
    const float* k  = (const float*)d_in[1];
    const float* v  = (const float*)d_in[2];
    const float* bw = (const float*)d_in[3];
    const int* ctx  = (const int*)d_in[4];
    const int* mem  = (const int*)d_in[5];
    const unsigned int* mask = (const unsigned int*)d_in[6];

    float* outp = (float*)d_out;                    // [2,16,2048,64]
    float* attn = outp + (size_t)2*16*2048*64;      // [2,16,2048,2048]
    float* pb   = attn + (size_t)2*16*2048*2048;    // [2,16,2048,2048]

    const int smem1 = 64*132*2*4;
    const int smem3 = (64*132 + 64*68)*4;
    cudaFuncSetAttribute(k1_scores, cudaFuncAttributeMaxDynamicSharedMemorySize, smem1);
    cudaFuncSetAttribute(k3_av,     cudaFuncAttributeMaxDynamicSharedMemorySize, smem3);

    dim3 g1(16, 16, 32);
    k1_scores<<<g1, 256, smem1>>>(q, k, bw, ctx, mem, mask, attn, pb);
    dim3 g3(16, 32);
    k3_av<<<g3, 128, smem3>>>(attn, v, outp);
}

// round 10
// speedup vs baseline: 1.2571x; 1.2571x over previous
#include <cuda_runtime.h>
#include <cstdint>
#include <cstddef>

#define SS 2048
#define DD 64
#define HH 16

// per-(bh,row, kt*2+khalf) partial sums of exp: 32*2048*32 floats = 8MB
__device__ float g_rowpart[(size_t)32 * 2048 * 32];

static __device__ __forceinline__ float2 ffma2(float2 a, float2 b, float2 c) {
    unsigned long long ua = *reinterpret_cast<unsigned long long*>(&a);
    unsigned long long ub = *reinterpret_cast<unsigned long long*>(&b);
    unsigned long long uc = *reinterpret_cast<unsigned long long*>(&c);
    unsigned long long ud;
    asm("fma.rn.f32x2 %0, %1, %2, %3;" : "=l"(ud) : "l"(ua), "l"(ub), "l"(uc));
    return *reinterpret_cast<float2*>(&ud);
}

// T5 bidirectional bucket, NUM_BUCKETS=32, MAX_DISTANCE=128 (exact int thresholds)
static __device__ __forceinline__ int rp_bucket(int rel) {
    int n = -rel;
    int ret = (n < 0) ? 16 : 0;
    n = abs(n);
    if (n < 8) return ret + n;
    return ret + 8 + (n >= 12) + (n >= 16) + (n >= 23) + (n >= 32)
                   + (n >= 46) + (n >= 64) + (n >= 91);
}

// K1: QK^T/8 + bias, masked -> exp(score) to attn, bias to pb, partials to g_rowpart.
// Warp shape 4qr x 8kc to halve K-side LDS wavefronts.
__global__ __launch_bounds__(256) void k1_scores(
    const float* __restrict__ qg, const float* __restrict__ kg,
    const float* __restrict__ bw, const int* __restrict__ ctx,
    const int* __restrict__ mem, const unsigned int* __restrict__ mask,
    float* __restrict__ attn, float* __restrict__ pb)
{
    extern __shared__ float smx[];
    float* Qs = smx;               // [64][132] d-major, swizzled rows
    float* Ks = smx + 64 * 132;
    __shared__ float bwsh[32];

    const int tid = threadIdx.x;
    const int kt = blockIdx.x, qt = blockIdx.y, bh = blockIdx.z;
    const int b = bh >> 4, h = bh & 15;
    if (tid < 32) bwsh[tid] = bw[tid * HH + h];

    const float4* qv = (const float4*)(qg + ((size_t)bh * SS + (size_t)qt * 128) * DD);
    const float4* kv = (const float4*)(kg + ((size_t)bh * SS + (size_t)kt * 128) * DD);
#pragma unroll
    for (int rep = 0; rep < 8; rep++) {
        int i4 = rep * 256 + tid;
        int row = i4 >> 4;
        int c4 = (i4 & 15) << 2;
        float4 a = qv[i4], bv = kv[i4];
        int r = row ^ (((c4 >> 2) & 7) << 2);
        Qs[(c4+0)*132 + r] = a.x;  Qs[(c4+1)*132 + r] = a.y;
        Qs[(c4+2)*132 + r] = a.z;  Qs[(c4+3)*132 + r] = a.w;
        Ks[(c4+0)*132 + r] = bv.x; Ks[(c4+1)*132 + r] = bv.y;
        Ks[(c4+2)*132 + r] = bv.z; Ks[(c4+3)*132 + r] = bv.w;
    }
    __syncthreads();

    // warp-internal 4x8 mapping: ty from tid bits {7,6,4,3}, tx from bits {5,2,1,0}
    const int ty = ((tid >> 6) << 2) | ((tid >> 3) & 3);
    const int tx = (((tid >> 5) & 1) << 3) | (tid & 7);
    const int khalf = (tid >> 5) & 1;          // == tx>>3, constant per warp
    const int qr = ty << 3, kc = tx << 3;

    float2 acc[8][4];
#pragma unroll
    for (int i = 0; i < 8; i++)
#pragma unroll
        for (int j = 0; j < 4; j++) acc[i][j] = make_float2(0.f, 0.f);

#pragma unroll 8
    for (int d = 0; d < 64; d++) {
        const float* Qd = Qs + d * 132;
        const float* Kd = Ks + d * 132;
        int fd = ((d >> 2) & 7) << 2;
        int rq = qr ^ fd, rk = kc ^ fd;
        float4 a0 = *(const float4*)(Qd + rq);
        float4 a1 = *(const float4*)(Qd + (rq ^ 4));
        float4 b0 = *(const float4*)(Kd + rk);
        float4 b1 = *(const float4*)(Kd + (rk ^ 4));
        float2 bp0 = make_float2(b0.x, b0.y), bp1 = make_float2(b0.z, b0.w);
        float2 bp2 = make_float2(b1.x, b1.y), bp3 = make_float2(b1.z, b1.w);
        float av[8] = {a0.x,a0.y,a0.z,a0.w,a1.x,a1.y,a1.z,a1.w};
#pragma unroll
        for (int i = 0; i < 8; i++) {
            float2 ap = make_float2(av[i], av[i]);
            acc[i][0] = ffma2(ap, bp0, acc[i][0]);
            acc[i][1] = ffma2(ap, bp1, acc[i][1]);
            acc[i][2] = ffma2(ap, bp2, acc[i][2]);
            acc[i][3] = ffma2(ap, bp3, acc[i][3]);
        }
    }

    const int qi0 = qt * 128 + qr;
    const int kj0 = kt * 128 + kc;
    int ctxv[8], memv[8];
#pragma unroll
    for (int i = 0; i < 8; i++) ctxv[i] = ctx[b * SS + qi0 + i];
#pragma unroll
    for (int j = 0; j < 8; j++) memv[j] = mem[b * SS + kj0 + j];

#pragma unroll
    for (int i = 0; i < 8; i++) {
        const int qi = qi0 + i;
        const size_t off = ((size_t)bh * SS + qi) * SS + kj0;
        const uint4 m0 = *(const uint4*)(mask + ((size_t)b * SS + qi) * SS + kj0);
        const uint4 m1 = *(const uint4*)(mask + ((size_t)b * SS + qi) * SS + kj0 + 4);
        unsigned int mw[8] = {m0.x, m0.y, m0.z, m0.w, m1.x, m1.y, m1.z, m1.w};
        float ev[8], pv[8];
#pragma unroll
        for (int j = 0; j < 8; j++) {
            float bias = bwsh[rp_bucket(memv[j] - ctxv[i])];
            pv[j] = bias;
            float s = ((j & 1) ? acc[i][j >> 1].y : acc[i][j >> 1].x) * 0.125f + bias;
            ev[j] = (mw[j] != 0u) ? 0.0f : __expf(s);
        }
        *(float4*)(attn + off)     = make_float4(ev[0], ev[1], ev[2], ev[3]);
        *(float4*)(attn + off + 4) = make_float4(ev[4], ev[5], ev[6], ev[7]);
        *(float4*)(pb + off)       = make_float4(pv[0], pv[1], pv[2], pv[3]);
        *(float4*)(pb + off + 4)   = make_float4(pv[4], pv[5], pv[6], pv[7]);

        // partial row sum: 8 lanes of this warp share (ty,khalf) -> cover 64 cols
        float ps = ev[0]+ev[1]+ev[2]+ev[3]+ev[4]+ev[5]+ev[6]+ev[7];
        ps += __shfl_xor_sync(0xffffffffu, ps, 1);
        ps += __shfl_xor_sync(0xffffffffu, ps, 2);
        ps += __shfl_xor_sync(0xffffffffu, ps, 4);
        if ((tid & 7) == 0)
            g_rowpart[((size_t)bh * SS + qi) * 32 + kt * 2 + khalf] = ps;
    }
}

// K2': finalize softmax: attn *= 1/rowsum (in place). 4 rows per CTA.
__global__ __launch_bounds__(256) void k2_scale(float* __restrict__ attn)
{
    __shared__ float inv[4];
    const size_t r0 = (size_t)blockIdx.x * 4;
    const int tid = threadIdx.x;
    if (tid < 4) {
        const float* pp = g_rowpart + (r0 + tid) * 32;
        float s = 0.f;
#pragma unroll
        for (int t = 0; t < 32; t++) s += pp[t];
        inv[tid] = 1.0f / s;
    }
    __syncthreads();
    float4* p = (float4*)attn + r0 * 512;
#pragma unroll
    for (int j = 0; j < 8; j++) {
        int idx = j * 256 + tid;
        float iv = inv[idx >> 9];
        float4 e = p[idx];
        e.x *= iv; e.y *= iv; e.z *= iv; e.w *= iv;
        p[idx] = e;
    }
}

// K3: output = attn @ V.  256 threads, tile 256q x 64d, micro 8x8, 2 CTAs/SM.
__global__ __launch_bounds__(256, 2) void k3_av(
    const float* __restrict__ attn, const float* __restrict__ vg,
    float* __restrict__ outp)
{
    extern __shared__ float smx[];
    float* As = smx;               // [64 k][264 q] swizzled
    float* Vs = smx + 64 * 264;    // [64 k][68 d]

    const int tid = threadIdx.x;
    const int qt = blockIdx.x, bh = blockIdx.y;
    const int ty = tid >> 3, tx = tid & 7;
    const int qr = ty << 3, dc = tx << 3;

    float2 acc[8][4];
#pragma unroll
    for (int i = 0; i < 8; i++)
#pragma unroll
        for (int j = 0; j < 4; j++) acc[i][j] = make_float2(0.f, 0.f);

    for (int kt = 0; kt < 32; kt++) {
        const float4* asrc = (const float4*)(attn + ((size_t)bh * SS + (size_t)qt * 256) * SS + kt * 64);
        const float4* vsrc = (const float4*)(vg + ((size_t)bh * SS + (size_t)kt * 64) * DD);

        // A tile 256q x 64k -> k-major swizzled
#pragma unroll
        for (int rep = 0; rep < 16; rep++) {
            int i4 = rep * 256 + tid;
            int row = i4 >> 4;            // q 0..255
            int c4 = (i4 & 15) << 2;      // k 0..60
            float4 e = asrc[row * 512 + (c4 >> 2)];
            int r = row ^ (((c4 >> 2) & 7) << 2);
            As[(c4+0)*264 + r] = e.x;  As[(c4+1)*264 + r] = e.y;
            As[(c4+2)*264 + r] = e.z;  As[(c4+3)*264 + r] = e.w;
        }
        // V tile 64k x 64d row-major
#pragma unroll
        for (int rep = 0; rep < 4; rep++) {
            int i4 = rep * 256 + tid;
            int row = i4 >> 4, c4 = (i4 & 15) << 2;
            *(float4*)(Vs + row * 68 + c4) = vsrc[row * 16 + (c4 >> 2)];
        }
        __syncthreads();

#pragma unroll 8
        for (int k = 0; k < 64; k++) {
            const float* Ak = As + k * 264;
            const float* Vk = Vs + k * 68 + dc;
            int fk = ((k >> 2) & 7) << 2;
            int rq = qr ^ fk;
            float4 a0 = *(const float4*)(Ak + rq);
            float4 a1 = *(const float4*)(Ak + (rq ^ 4));
            float4 v0 = *(const float4*)(Vk);
            float4 v1 = *(const float4*)(Vk + 4);
            float2 vp0 = make_float2(v0.x, v0.y), vp1 = make_float2(v0.z, v0.w);
            float2 vp2 = make_float2(v1.x, v1.y), vp3 = make_float2(v1.z, v1.w);
            float av[8] = {a0.x,a0.y,a0.z,a0.w,a1.x,a1.y,a1.z,a1.w};
#pragma unroll
            for (int i = 0; i < 8; i++) {
                float2 ap = make_float2(av[i], av[i]);
                acc[i][0] = ffma2(ap, vp0, acc[i][0]);
                acc[i][1] = ffma2(ap, vp1, acc[i][1]);
                acc[i][2] = ffma2(ap, vp2, acc[i][2]);
                acc[i][3] = ffma2(ap, vp3, acc[i][3]);
            }
        }
        __syncthreads();
    }

#pragma unroll
    for (int i = 0; i < 8; i++) {
        size_t off = ((size_t)bh * SS + (size_t)qt * 256 + qr + i) * DD + dc;
        *(float4*)(outp + off)     = make_float4(acc[i][0].x, acc[i][0].y, acc[i][1].x, acc[i][1].y);
        *(float4*)(outp + off + 4) = make_float4(acc[i][2].x, acc[i][2].y, acc[i][3].x, acc[i][3].y);
    }
}

extern "C" void kernel_launch(void* const* d_in, const int* in_sizes, int n_in,
                              void* d_out, int out_size)
{
    const float* q  = (const float*)d_in[0];
    const float* k  = (const float*)d_in[1];
    const float* v  = (const float*)d_in[2];
    const float* bw = (const float*)d_in[3];
    const int* ctx  = (const int*)d_in[4];
    const int* mem  = (const int*)d_in[5];
    const unsigned int* mask = (const unsigned int*)d_in[6];

    float* outp = (float*)d_out;                    // [2,16,2048,64]
    float* attn = outp + (size_t)2*16*2048*64;      // [2,16,2048,2048]
    float* pb   = attn + (size_t)2*16*2048*2048;    // [2,16,2048,2048]

    const int smem1 = 64*132*2*4;
    const int smem3 = (64*264 + 64*68)*4;
    cudaFuncSetAttribute(k1_scores, cudaFuncAttributeMaxDynamicSharedMemorySize, smem1);
    cudaFuncSetAttribute(k3_av,     cudaFuncAttributeMaxDynamicSharedMemorySize, smem3);

    dim3 g1(16, 16, 32);
    k1_scores<<<g1, 256, smem1>>>(q, k, bw, ctx, mem, mask, attn, pb);
    k2_scale<<<32*2048/4, 256>>>(attn);
    dim3 g3(8, 32);
    k3_av<<<g3, 256, smem3>>>(attn, v, outp);
}